// round 3
// baseline (speedup 1.0000x reference)
#include <cuda_runtime.h>
#include <cuda_bf16.h>

#define E_TOTAL 1600000
#define NN      100000
#define PADW    68          // 64 + 4 padding to break smem bank conflicts

// Scratch (allocation-free rule: __device__ globals)
__device__ float g_summed[NN * 64];
__device__ float g_counts[NN];

extern __shared__ float smem[];

// ---------------------------------------------------------------------------
// Kernel 1: fused edge-MLP + atomic scatter.
// Tile: 64 edges/block, 256 threads, each thread owns a 4x4 micro-tile.
//   hidden = relu([x[col], edge_attr] @ W1a + b1a)      (64 -> 64)
//   m      = hidden @ W1b + b1b                          (64 -> 64)
//   atomicAdd into g_summed[row], atomicAdd 1 into g_counts[row]
// ---------------------------------------------------------------------------
__global__ __launch_bounds__(256) void edge_kernel(
    const float* __restrict__ x,
    const int* __restrict__ eidx,          // int32! harness coerces int64 -> int32
    const float* __restrict__ eattr,
    const float* __restrict__ W1a, const float* __restrict__ b1a,
    const float* __restrict__ W1b, const float* __restrict__ b1b)
{
    float* sW1a = smem;                     // 64*64
    float* sW1b = sW1a + 4096;              // 64*64
    float* sB1a = sW1b + 4096;              // 64
    float* sB1b = sB1a + 64;                // 64
    float* inT  = sB1b + 64;                // [64 k][68] transposed input tile
    float* hT   = inT + 64 * PADW;          // [64 j][68] transposed hidden tile
    int*   sRow = (int*)(hT + 64 * PADW);   // 64
    int*   sCol = sRow + 64;                // 64

    const int t = threadIdx.x;
    const int ebase = blockIdx.x * 64;

    // Stage weights (coalesced float4)
    {
        const float4* gA = (const float4*)W1a;
        const float4* gB = (const float4*)W1b;
        float4* sA = (float4*)sW1a;
        float4* sB = (float4*)sW1b;
#pragma unroll
        for (int i = 0; i < 4; i++) {
            sA[t + 256 * i] = gA[t + 256 * i];
            sB[t + 256 * i] = gB[t + 256 * i];
        }
    }
    if (t < 64) {
        sB1a[t] = b1a[t];
        sB1b[t] = b1b[t];
        sRow[t] = eidx[ebase + t];
        sCol[t] = eidx[E_TOTAL + ebase + t];
    }
    __syncthreads();

    // Stage input tile transposed: inT[k][e]; k<32: x[col[e]][k], k>=32: eattr[e][k-32]
    {
        const int f4 = t & 7;       // which float4 of the 32-feature row
        const int e  = t >> 3;      // 32 edges per pass
#pragma unroll
        for (int pass = 0; pass < 2; pass++) {
            const int ee = e + pass * 32;
            float4 v = ((const float4*)eattr)[(ebase + ee) * 8 + f4];
            inT[(32 + f4 * 4 + 0) * PADW + ee] = v.x;
            inT[(32 + f4 * 4 + 1) * PADW + ee] = v.y;
            inT[(32 + f4 * 4 + 2) * PADW + ee] = v.z;
            inT[(32 + f4 * 4 + 3) * PADW + ee] = v.w;
            float4 g = ((const float4*)x)[sCol[ee] * 8 + f4];
            inT[(f4 * 4 + 0) * PADW + ee] = g.x;
            inT[(f4 * 4 + 1) * PADW + ee] = g.y;
            inT[(f4 * 4 + 2) * PADW + ee] = g.z;
            inT[(f4 * 4 + 3) * PADW + ee] = g.w;
        }
    }
    __syncthreads();

    const int e0 = (t & 15) * 4;   // 4 edges
    const int j0 = (t >> 4) * 4;   // 4 hidden features

    // ---- Layer 1: acc[ee][jj] = sum_k inT[k][e0+ee] * W1a[k][j0+jj] ----
    float acc[4][4];
#pragma unroll
    for (int i = 0; i < 4; i++)
#pragma unroll
        for (int j = 0; j < 4; j++) acc[i][j] = 0.f;

#pragma unroll 8
    for (int k = 0; k < 64; k++) {
        const float4 av = *(const float4*)&inT[k * PADW + e0];
        const float4 wv = *(const float4*)&sW1a[k * 64 + j0];
        const float a[4] = {av.x, av.y, av.z, av.w};
        const float w[4] = {wv.x, wv.y, wv.z, wv.w};
#pragma unroll
        for (int i = 0; i < 4; i++)
#pragma unroll
            for (int j = 0; j < 4; j++) acc[i][j] += a[i] * w[j];
    }

    // bias + relu, store transposed for layer 2: hT[j][e]
#pragma unroll
    for (int j = 0; j < 4; j++) {
        const float b = sB1a[j0 + j];
        float4 v;
        v.x = fmaxf(acc[0][j] + b, 0.f);
        v.y = fmaxf(acc[1][j] + b, 0.f);
        v.z = fmaxf(acc[2][j] + b, 0.f);
        v.w = fmaxf(acc[3][j] + b, 0.f);
        *(float4*)&hT[(j0 + j) * PADW + e0] = v;
    }
    __syncthreads();

    // ---- Layer 2: m[ee][jj] = sum_k hT[k][e0+ee] * W1b[k][j0+jj] + b1b ----
#pragma unroll
    for (int i = 0; i < 4; i++)
#pragma unroll
        for (int j = 0; j < 4; j++) acc[i][j] = 0.f;

#pragma unroll 8
    for (int k = 0; k < 64; k++) {
        const float4 av = *(const float4*)&hT[k * PADW + e0];
        const float4 wv = *(const float4*)&sW1b[k * 64 + j0];
        const float a[4] = {av.x, av.y, av.z, av.w};
        const float w[4] = {wv.x, wv.y, wv.z, wv.w};
#pragma unroll
        for (int i = 0; i < 4; i++)
#pragma unroll
            for (int j = 0; j < 4; j++) acc[i][j] += a[i] * w[j];
    }

    // Atomic scatter into destination nodes
#pragma unroll
    for (int i = 0; i < 4; i++) {
        const int r = sRow[e0 + i];
        float* base = &g_summed[r * 64 + j0];
#pragma unroll
        for (int j = 0; j < 4; j++)
            atomicAdd(&base[j], acc[i][j] + sB1b[j0 + j]);
    }
    if (t < 64) atomicAdd(&g_counts[sRow[t]], 1.0f);
}

// ---------------------------------------------------------------------------
// Kernel 2: node MLP.
//   agg = summed / max(counts,1);  h = relu([x, agg] @ W2a + b2a)
//   out = h @ W2b + b2b
// Tile: 64 nodes/block, 256 threads.
// ---------------------------------------------------------------------------
__global__ __launch_bounds__(256) void node_kernel(
    const float* __restrict__ x,
    const float* __restrict__ W2a, const float* __restrict__ b2a,
    const float* __restrict__ W2b, const float* __restrict__ b2b,
    float* __restrict__ out)
{
    float* sW2a = smem;                    // 96*64
    float* sW2b = sW2a + 6144;             // 64*32
    float* sB2a = sW2b + 2048;             // 64
    float* sB2b = sB2a + 64;               // 32
    float* inT  = sB2b + 32;               // [96 k][68]
    float* hT   = inT + 96 * PADW;         // [64 j][68]

    const int t = threadIdx.x;
    const int n0 = blockIdx.x * 64;

    // Stage weights
    {
        const float4* gA = (const float4*)W2a;
        float4* sA = (float4*)sW2a;
#pragma unroll
        for (int i = 0; i < 6; i++) sA[t + 256 * i] = gA[t + 256 * i];
        const float4* gB = (const float4*)W2b;
        float4* sB = (float4*)sW2b;
#pragma unroll
        for (int i = 0; i < 2; i++) sB[t + 256 * i] = gB[t + 256 * i];
    }
    if (t < 64) sB2a[t] = b2a[t];
    if (t < 32) sB2b[t] = b2b[t];

    // Stage x part of input tile (k = 0..31)
    {
        const int f4 = t & 7;
        const int n  = t >> 3;
#pragma unroll
        for (int pass = 0; pass < 2; pass++) {
            const int nn = n + pass * 32;
            const int node = n0 + nn;
            float4 v = make_float4(0.f, 0.f, 0.f, 0.f);
            if (node < NN) v = ((const float4*)x)[node * 8 + f4];
            inT[(f4 * 4 + 0) * PADW + nn] = v.x;
            inT[(f4 * 4 + 1) * PADW + nn] = v.y;
            inT[(f4 * 4 + 2) * PADW + nn] = v.z;
            inT[(f4 * 4 + 3) * PADW + nn] = v.w;
        }
    }
    // Stage agg part (k = 32..95): summed / max(count,1)
    {
        const int j4 = t & 15;
        const int n  = t >> 4;
#pragma unroll
        for (int pass = 0; pass < 4; pass++) {
            const int nn = n + pass * 16;
            const int node = n0 + nn;
            float4 v = make_float4(0.f, 0.f, 0.f, 0.f);
            if (node < NN) {
                const float inv = 1.0f / fmaxf(g_counts[node], 1.0f);
                v = ((const float4*)g_summed)[node * 16 + j4];
                v.x *= inv; v.y *= inv; v.z *= inv; v.w *= inv;
            }
            inT[(32 + j4 * 4 + 0) * PADW + nn] = v.x;
            inT[(32 + j4 * 4 + 1) * PADW + nn] = v.y;
            inT[(32 + j4 * 4 + 2) * PADW + nn] = v.z;
            inT[(32 + j4 * 4 + 3) * PADW + nn] = v.w;
        }
    }
    __syncthreads();

    const int e0 = (t & 15) * 4;

    // ---- Layer A: 96 -> 64, relu ----
    {
        const int j0 = (t >> 4) * 4;
        float acc[4][4];
#pragma unroll
        for (int i = 0; i < 4; i++)
#pragma unroll
            for (int j = 0; j < 4; j++) acc[i][j] = 0.f;

#pragma unroll 8
        for (int k = 0; k < 96; k++) {
            const float4 av = *(const float4*)&inT[k * PADW + e0];
            const float4 wv = *(const float4*)&sW2a[k * 64 + j0];
            const float a[4] = {av.x, av.y, av.z, av.w};
            const float w[4] = {wv.x, wv.y, wv.z, wv.w};
#pragma unroll
            for (int i = 0; i < 4; i++)
#pragma unroll
                for (int j = 0; j < 4; j++) acc[i][j] += a[i] * w[j];
        }
#pragma unroll
        for (int j = 0; j < 4; j++) {
            const float b = sB2a[j0 + j];
            float4 v;
            v.x = fmaxf(acc[0][j] + b, 0.f);
            v.y = fmaxf(acc[1][j] + b, 0.f);
            v.z = fmaxf(acc[2][j] + b, 0.f);
            v.w = fmaxf(acc[3][j] + b, 0.f);
            *(float4*)&hT[(j0 + j) * PADW + e0] = v;
        }
    }
    __syncthreads();

    // ---- Layer B: 64 -> 32, write output ----
    if (t < 128) {
        const int o0 = (t >> 4) * 4;   // 8 groups * 4 = 32 outputs
        float acc[4][4];
#pragma unroll
        for (int i = 0; i < 4; i++)
#pragma unroll
            for (int j = 0; j < 4; j++) acc[i][j] = 0.f;

#pragma unroll 8
        for (int k = 0; k < 64; k++) {
            const float4 av = *(const float4*)&hT[k * PADW + e0];
            const float4 wv = *(const float4*)&sW2b[k * 32 + o0];
            const float a[4] = {av.x, av.y, av.z, av.w};
            const float w[4] = {wv.x, wv.y, wv.z, wv.w};
#pragma unroll
            for (int i = 0; i < 4; i++)
#pragma unroll
                for (int j = 0; j < 4; j++) acc[i][j] += a[i] * w[j];
        }
#pragma unroll
        for (int i = 0; i < 4; i++) {
            const int node = n0 + e0 + i;
            if (node < NN) {
                float4 v;
                v.x = acc[i][0] + sB2b[o0 + 0];
                v.y = acc[i][1] + sB2b[o0 + 1];
                v.z = acc[i][2] + sB2b[o0 + 2];
                v.w = acc[i][3] + sB2b[o0 + 3];
                *(float4*)&out[node * 32 + o0] = v;
            }
        }
    }
}

// ---------------------------------------------------------------------------
extern "C" void kernel_launch(void* const* d_in, const int* in_sizes, int n_in,
                              void* d_out, int out_size)
{
    const float* x     = (const float*)d_in[0];
    const int*   eidx  = (const int*)d_in[1];    // int64 coerced to int32 by harness
    const float* eattr = (const float*)d_in[2];
    // d_in[3] = u (unused), d_in[4] = batch (unused)
    const float* W1a = (const float*)d_in[5];
    const float* b1a = (const float*)d_in[6];
    const float* W1b = (const float*)d_in[7];
    const float* b1b = (const float*)d_in[8];
    const float* W2a = (const float*)d_in[9];
    const float* b2a = (const float*)d_in[10];
    const float* W2b = (const float*)d_in[11];
    const float* b2b = (const float*)d_in[12];
    float* out = (float*)d_out;

    const size_t smem1 = (4096 + 4096 + 64 + 64 + 64 * PADW + 64 * PADW) * sizeof(float)
                         + 128 * sizeof(int);
    const size_t smem2 = (6144 + 2048 + 64 + 32 + 96 * PADW + 64 * PADW) * sizeof(float);

    cudaFuncSetAttribute(edge_kernel, cudaFuncAttributeMaxDynamicSharedMemorySize, (int)smem1);
    cudaFuncSetAttribute(node_kernel, cudaFuncAttributeMaxDynamicSharedMemorySize, (int)smem2);

    void* p_summed = nullptr;
    void* p_counts = nullptr;
    cudaGetSymbolAddress(&p_summed, g_summed);
    cudaGetSymbolAddress(&p_counts, g_counts);
    cudaMemsetAsync(p_summed, 0, (size_t)NN * 64 * sizeof(float));
    cudaMemsetAsync(p_counts, 0, (size_t)NN * sizeof(float));

    edge_kernel<<<E_TOTAL / 64, 256, smem1>>>(x, eidx, eattr, W1a, b1a, W1b, b1b);
    node_kernel<<<(NN + 63) / 64, 256, smem2>>>(x, W2a, b2a, W2b, b2b, out);
}

// round 10
// speedup vs baseline: 1.3555x; 1.3555x over previous
#include <cuda_runtime.h>
#include <cuda_bf16.h>
#include <mma.h>
#include <cstdint>

using namespace nvcuda;

#define E_TOTAL 1600000
#define NN      100000
#define NTILES  (E_TOTAL / 128)   // 12500
#define PADW    68                // node kernel padding
#define LDA     68                // edge kernel smem stride (mult of 4, breaks conflicts)

// Scratch (allocation-free rule: __device__ globals)
__device__ float g_summed[NN * 64];
__device__ float g_counts[NN];

__device__ __forceinline__ void red_add_v4(float* p, float a, float b, float c, float d) {
    asm volatile("red.global.add.v4.f32 [%0], {%1, %2, %3, %4};"
                 :: "l"(p), "f"(a), "f"(b), "f"(c), "f"(d) : "memory");
}

// Dynamic smem layout for edge kernel, in floats:
//   sW1a [64][68], sW1b [64][68], b1a[64], b1b[64], inA [128][68], hid [128][68]
#define W1A_OFF  0
#define W1B_OFF  4352
#define B1A_OFF  8704
#define B1B_OFF  8768
#define INA_OFF  8832
#define HID_OFF  17536
#define EDGE_SMEM_FLOATS 26240   // 104,960 bytes -> 2 CTAs/SM

extern __shared__ float esm[];

// ---------------------------------------------------------------------------
// Edge kernel: persistent, tf32 wmma (HMMA.1688). 128 edges/tile, 8 warps,
// each warp owns a fully independent 16-edge pipeline (no block barriers in loop).
// ---------------------------------------------------------------------------
__global__ __launch_bounds__(256) void edge_kernel_wmma(
    const float* __restrict__ x,
    const int* __restrict__ eidx,
    const float* __restrict__ eattr,
    const float* __restrict__ W1a, const float* __restrict__ b1a,
    const float* __restrict__ W1b, const float* __restrict__ b1b)
{
    const int tid = threadIdx.x;
    const int w   = tid >> 5;      // warp 0..7
    const int ln  = tid & 31;

    float* sW1a = esm + W1A_OFF;
    float* sW1b = esm + W1B_OFF;
    float* sb1a = esm + B1A_OFF;
    float* sb1b = esm + B1B_OFF;
    float* inA  = esm + INA_OFF;   // [128][LDA]
    float* hid  = esm + HID_OFF;   // [128][LDA]

    // ---- stage weights (tf32-converted) + biases, once per CTA ----
    for (int idx = tid; idx < 4096; idx += 256) {
        const int k = idx >> 6, n = idx & 63;
        sW1a[k * LDA + n] = wmma::__float_to_tf32(W1a[idx]);
        sW1b[k * LDA + n] = wmma::__float_to_tf32(W1b[idx]);
    }
    if (tid < 64) {
        sb1a[tid] = b1a[tid];
        sb1b[tid] = b1b[tid];
    }
    __syncthreads();

    // Per-warp constants
    const int i    = ln >> 1;          // edge-in-warp 0..15
    const int half = ln & 1;           // feature half (0: x[col], 1: eattr)
    const int r0   = w * 16;           // my warp's row block in smem tiles
    const int myrow = r0 + i;

    wmma::fragment<wmma::matrix_a, 16, 16, 8, wmma::precision::tf32, wmma::row_major> af;
    wmma::fragment<wmma::matrix_b, 16, 16, 8, wmma::precision::tf32, wmma::row_major> bf;
    wmma::fragment<wmma::accumulator, 16, 16, 8, float> acc[4];

    for (int tile = blockIdx.x; tile < NTILES; tile += gridDim.x) {
        const int e0 = tile * 128 + r0;   // this warp's first edge
        const int e  = e0 + i;            // this lane-pair's edge

        // ---- gather: inA[myrow][half*32 .. +32] = tf32([x[col]] or [eattr]) ----
        {
            const int col = eidx[E_TOTAL + e];
            const float4* src = half ? (const float4*)(eattr + (size_t)e * 32)
                                     : (const float4*)(x + (size_t)col * 32);
            float* dst = inA + myrow * LDA + half * 32;
#pragma unroll
            for (int q = 0; q < 8; q++) {
                float4 v = src[q];
                float4 t;
                t.x = wmma::__float_to_tf32(v.x);
                t.y = wmma::__float_to_tf32(v.y);
                t.z = wmma::__float_to_tf32(v.z);
                t.w = wmma::__float_to_tf32(v.w);
                *(float4*)(dst + q * 4) = t;
            }
        }
        __syncwarp();

        // ---- layer 1: hid[r0..r0+15][0..63] = inA @ W1a ----
#pragma unroll
        for (int n = 0; n < 4; n++) wmma::fill_fragment(acc[n], 0.0f);
#pragma unroll
        for (int k = 0; k < 8; k++) {
            wmma::load_matrix_sync(af, inA + r0 * LDA + k * 8, LDA);
#pragma unroll
            for (int n = 0; n < 4; n++) {
                wmma::load_matrix_sync(bf, sW1a + (k * 8) * LDA + n * 16, LDA);
                wmma::mma_sync(acc[n], af, bf, acc[n]);
            }
        }
#pragma unroll
        for (int n = 0; n < 4; n++)
            wmma::store_matrix_sync(hid + r0 * LDA + n * 16, acc[n], LDA, wmma::mem_row_major);
        __syncwarp();

        // ---- bias + relu + tf32 requantize (in place, own rows only) ----
        {
            float* hrow = hid + myrow * LDA + half * 32;
            const float* brow = sb1a + half * 32;
#pragma unroll
            for (int q = 0; q < 8; q++) {
                float4 v = *(float4*)(hrow + q * 4);
                v.x = wmma::__float_to_tf32(fmaxf(v.x + brow[q * 4 + 0], 0.f));
                v.y = wmma::__float_to_tf32(fmaxf(v.y + brow[q * 4 + 1], 0.f));
                v.z = wmma::__float_to_tf32(fmaxf(v.z + brow[q * 4 + 2], 0.f));
                v.w = wmma::__float_to_tf32(fmaxf(v.w + brow[q * 4 + 3], 0.f));
                *(float4*)(hrow + q * 4) = v;
            }
        }
        __syncwarp();

        // ---- layer 2: inA[r0..][0..63] = hid @ W1b  (reuses inA as D buffer) ----
#pragma unroll
        for (int n = 0; n < 4; n++) wmma::fill_fragment(acc[n], 0.0f);
#pragma unroll
        for (int k = 0; k < 8; k++) {
            wmma::load_matrix_sync(af, hid + r0 * LDA + k * 8, LDA);
#pragma unroll
            for (int n = 0; n < 4; n++) {
                wmma::load_matrix_sync(bf, sW1b + (k * 8) * LDA + n * 16, LDA);
                wmma::mma_sync(acc[n], af, bf, acc[n]);
            }
        }
#pragma unroll
        for (int n = 0; n < 4; n++)
            wmma::store_matrix_sync(inA + r0 * LDA + n * 16, acc[n], LDA, wmma::mem_row_major);
        __syncwarp();

        // ---- scatter: g_summed[row] += D + b1b ----
        {
            const int row = eidx[e];
            const float* drow = inA + myrow * LDA + half * 32;
            const float* brow = sb1b + half * 32;
            float* base = g_summed + (size_t)row * 64 + half * 32;
#pragma unroll
            for (int q = 0; q < 8; q++) {
                float4 v = *(float4*)(drow + q * 4);
                red_add_v4(base + q * 4,
                           v.x + brow[q * 4 + 0], v.y + brow[q * 4 + 1],
                           v.z + brow[q * 4 + 2], v.w + brow[q * 4 + 3]);
            }
            if (!half) atomicAdd(&g_counts[row], 1.0f);
        }
        __syncwarp();
    }
}

// ---------------------------------------------------------------------------
// Node kernel (fp32 path — 63 us measured)
// ---------------------------------------------------------------------------
extern __shared__ float smemf[];

__global__ __launch_bounds__(256) void node_kernel(
    const float* __restrict__ x,
    const float* __restrict__ W2a, const float* __restrict__ b2a,
    const float* __restrict__ W2b, const float* __restrict__ b2b,
    float* __restrict__ out)
{
    float* sW2a = smemf;                   // 96*64
    float* sW2b = sW2a + 6144;             // 64*32
    float* sB2a = sW2b + 2048;             // 64
    float* sB2b = sB2a + 64;               // 32
    float* inT  = sB2b + 32;               // [96 k][68]
    float* hT   = inT + 96 * PADW;         // [64 j][68]

    const int t = threadIdx.x;
    const int n0 = blockIdx.x * 64;

    {
        const float4* gA = (const float4*)W2a;
        float4* sA = (float4*)sW2a;
#pragma unroll
        for (int i = 0; i < 6; i++) sA[t + 256 * i] = gA[t + 256 * i];
        const float4* gB = (const float4*)W2b;
        float4* sB = (float4*)sW2b;
#pragma unroll
        for (int i = 0; i < 2; i++) sB[t + 256 * i] = gB[t + 256 * i];
    }
    if (t < 64) sB2a[t] = b2a[t];
    if (t < 32) sB2b[t] = b2b[t];

    {
        const int f4 = t & 7;
        const int n  = t >> 3;
#pragma unroll
        for (int pass = 0; pass < 2; pass++) {
            const int nn = n + pass * 32;
            const int node = n0 + nn;
            float4 v = make_float4(0.f, 0.f, 0.f, 0.f);
            if (node < NN) v = ((const float4*)x)[node * 8 + f4];
            inT[(f4 * 4 + 0) * PADW + nn] = v.x;
            inT[(f4 * 4 + 1) * PADW + nn] = v.y;
            inT[(f4 * 4 + 2) * PADW + nn] = v.z;
            inT[(f4 * 4 + 3) * PADW + nn] = v.w;
        }
    }
    {
        const int j4 = t & 15;
        const int n  = t >> 4;
#pragma unroll
        for (int pass = 0; pass < 4; pass++) {
            const int nn = n + pass * 16;
            const int node = n0 + nn;
            float4 v = make_float4(0.f, 0.f, 0.f, 0.f);
            if (node < NN) {
                const float inv = 1.0f / fmaxf(g_counts[node], 1.0f);
                v = ((const float4*)g_summed)[node * 16 + j4];
                v.x *= inv; v.y *= inv; v.z *= inv; v.w *= inv;
            }
            inT[(32 + j4 * 4 + 0) * PADW + nn] = v.x;
            inT[(32 + j4 * 4 + 1) * PADW + nn] = v.y;
            inT[(32 + j4 * 4 + 2) * PADW + nn] = v.z;
            inT[(32 + j4 * 4 + 3) * PADW + nn] = v.w;
        }
    }
    __syncthreads();

    const int e0 = (t & 15) * 4;

    {
        const int j0 = (t >> 4) * 4;
        float acc[4][4];
#pragma unroll
        for (int i = 0; i < 4; i++)
#pragma unroll
            for (int j = 0; j < 4; j++) acc[i][j] = 0.f;

#pragma unroll 8
        for (int k = 0; k < 96; k++) {
            const float4 av = *(const float4*)&inT[k * PADW + e0];
            const float4 wv = *(const float4*)&sW2a[k * 64 + j0];
            const float aa[4] = {av.x, av.y, av.z, av.w};
            const float ww[4] = {wv.x, wv.y, wv.z, wv.w};
#pragma unroll
            for (int i = 0; i < 4; i++)
#pragma unroll
                for (int j = 0; j < 4; j++) acc[i][j] += aa[i] * ww[j];
        }
#pragma unroll
        for (int j = 0; j < 4; j++) {
            const float b = sB2a[j0 + j];
            float4 v;
            v.x = fmaxf(acc[0][j] + b, 0.f);
            v.y = fmaxf(acc[1][j] + b, 0.f);
            v.z = fmaxf(acc[2][j] + b, 0.f);
            v.w = fmaxf(acc[3][j] + b, 0.f);
            *(float4*)&hT[(j0 + j) * PADW + e0] = v;
        }
    }
    __syncthreads();

    if (t < 128) {
        const int o0 = (t >> 4) * 4;
        float acc[4][4];
#pragma unroll
        for (int i = 0; i < 4; i++)
#pragma unroll
            for (int j = 0; j < 4; j++) acc[i][j] = 0.f;

#pragma unroll 8
        for (int k = 0; k < 64; k++) {
            const float4 av = *(const float4*)&hT[k * PADW + e0];
            const float4 wv = *(const float4*)&sW2b[k * 32 + o0];
            const float aa[4] = {av.x, av.y, av.z, av.w};
            const float ww[4] = {wv.x, wv.y, wv.z, wv.w};
#pragma unroll
            for (int i = 0; i < 4; i++)
#pragma unroll
                for (int j = 0; j < 4; j++) acc[i][j] += aa[i] * ww[j];
        }
#pragma unroll
        for (int i = 0; i < 4; i++) {
            const int node = n0 + e0 + i;
            if (node < NN) {
                float4 v;
                v.x = acc[i][0] + sB2b[o0 + 0];
                v.y = acc[i][1] + sB2b[o0 + 1];
                v.z = acc[i][2] + sB2b[o0 + 2];
                v.w = acc[i][3] + sB2b[o0 + 3];
                *(float4*)&out[node * 32 + o0] = v;
            }
        }
    }
}

// ---------------------------------------------------------------------------
extern "C" void kernel_launch(void* const* d_in, const int* in_sizes, int n_in,
                              void* d_out, int out_size)
{
    const float* x     = (const float*)d_in[0];
    const int*   eidx  = (const int*)d_in[1];    // int64 coerced to int32 by harness
    const float* eattr = (const float*)d_in[2];
    const float* W1a = (const float*)d_in[5];
    const float* b1a = (const float*)d_in[6];
    const float* W1b = (const float*)d_in[7];
    const float* b1b = (const float*)d_in[8];
    const float* W2a = (const float*)d_in[9];
    const float* b2a = (const float*)d_in[10];
    const float* W2b = (const float*)d_in[11];
    const float* b2b = (const float*)d_in[12];
    float* out = (float*)d_out;

    const size_t smem1 = EDGE_SMEM_FLOATS * sizeof(float);
    const size_t smem2 = (6144 + 2048 + 64 + 32 + 96 * PADW + 64 * PADW) * sizeof(float);

    cudaFuncSetAttribute(edge_kernel_wmma, cudaFuncAttributeMaxDynamicSharedMemorySize, (int)smem1);
    cudaFuncSetAttribute(node_kernel, cudaFuncAttributeMaxDynamicSharedMemorySize, (int)smem2);

    void* p_summed = nullptr;
    void* p_counts = nullptr;
    cudaGetSymbolAddress(&p_summed, g_summed);
    cudaGetSymbolAddress(&p_counts, g_counts);
    cudaMemsetAsync(p_summed, 0, (size_t)NN * 64 * sizeof(float));
    cudaMemsetAsync(p_counts, 0, (size_t)NN * sizeof(float));

    edge_kernel_wmma<<<296, 256, smem1>>>(x, eidx, eattr, W1a, b1a, W1b, b1b);
    node_kernel<<<(NN + 63) / 64, 256, smem2>>>(x, W2a, b2a, W2b, b2b, out);
}

// round 11
// speedup vs baseline: 1.7239x; 1.2717x over previous
#include <cuda_runtime.h>
#include <cuda_bf16.h>
#include <mma.h>
#include <cstdint>

using namespace nvcuda;

#define E_TOTAL 1600000
#define NN      100000
#define NTILES  (E_TOTAL / 128)   // 12500
#define PADW    68                // node kernel padding
#define LDB     72                // bf16 smem stride (72 el = 144 B, mult of 16 B)
#define LDD     68                // fp32 D-scratch stride

// Scratch (allocation-free rule: __device__ globals)
__device__ float g_summed[NN * 64];
__device__ float g_counts[NN];

__device__ __forceinline__ void red_add_v4(float* p, float a, float b, float c, float d) {
    asm volatile("red.global.add.v4.f32 [%0], {%1, %2, %3, %4};"
                 :: "l"(p), "f"(a), "f"(b), "f"(c), "f"(d) : "memory");
}
__device__ __forceinline__ uint32_t pack_bf16x2(float lo, float hi) {
    __nv_bfloat162 h = __floats2bfloat162_rn(lo, hi);
    return *(uint32_t*)&h;
}

// Edge-kernel dynamic smem (byte offsets; all 16B aligned):
//   sW1a bf16[64][72]  @0      (9216 B)
//   sW1b bf16[64][72]  @9216   (9216 B)
//   inA  bf16[128][72] @18432  (18432 B)   A tile; rewritten in place as hidden
//   sD   f32 [128][68] @36864  (34816 B)   per-warp-private D scratch (own rows)
//   b1a  f32 [64]      @71680
//   b1b  f32 [64]      @71936
#define EDGE_SMEM_BYTES 72192    // -> 3 CTAs/SM (216.6 KB of 228 KB)

extern __shared__ char esm8[];

// ---------------------------------------------------------------------------
// Edge kernel: persistent, bf16 wmma (HMMA.16816 + LDSM). 128 edges/tile,
// 8 warps, each warp owns an independent 16-edge pipeline (no block barriers
// in the steady loop).
// ---------------------------------------------------------------------------
__global__ __launch_bounds__(256) void edge_kernel_bf16(
    const float* __restrict__ x,
    const int* __restrict__ eidx,
    const float* __restrict__ eattr,
    const float* __restrict__ W1a, const float* __restrict__ b1a,
    const float* __restrict__ W1b, const float* __restrict__ b1b)
{
    const int tid = threadIdx.x;
    const int w   = tid >> 5;
    const int ln  = tid & 31;

    __nv_bfloat16* sW1a = (__nv_bfloat16*)(esm8);
    __nv_bfloat16* sW1b = (__nv_bfloat16*)(esm8 + 9216);
    __nv_bfloat16* inA  = (__nv_bfloat16*)(esm8 + 18432);
    float* sD   = (float*)(esm8 + 36864);
    float* sb1a = (float*)(esm8 + 71680);
    float* sb1b = (float*)(esm8 + 71936);

    // ---- stage weights (bf16) + biases, once per CTA ----
    for (int idx = tid; idx < 4096; idx += 256) {
        const int k = idx >> 6, n = idx & 63;
        sW1a[k * LDB + n] = __float2bfloat16(W1a[idx]);
        sW1b[k * LDB + n] = __float2bfloat16(W1b[idx]);
    }
    if (tid < 64) {
        sb1a[tid] = b1a[tid];
        sb1b[tid] = b1b[tid];
    }
    __syncthreads();

    const int i    = ln >> 1;      // edge-in-warp 0..15
    const int half = ln & 1;       // feature half (0: x[col], 1: eattr)
    const int r0   = w * 16;
    const int myrow = r0 + i;

    wmma::fragment<wmma::matrix_a, 16, 16, 16, __nv_bfloat16, wmma::row_major> af;
    wmma::fragment<wmma::matrix_b, 16, 16, 16, __nv_bfloat16, wmma::row_major> bf;
    wmma::fragment<wmma::accumulator, 16, 16, 16, float> acc[4];

    for (int tile = blockIdx.x; tile < NTILES; tile += gridDim.x) {
        const int e = tile * 128 + myrow;

        // ---- gather: inA[myrow][half*32..+32] = bf16([x[col]] or [eattr]) ----
        {
            const int col = eidx[E_TOTAL + e];
            const float4* src = half ? (const float4*)(eattr + (size_t)e * 32)
                                     : (const float4*)(x + (size_t)col * 32);
            uint4* dst = (uint4*)(inA + myrow * LDB + half * 32);
#pragma unroll
            for (int q = 0; q < 4; q++) {
                float4 a = src[2 * q], b = src[2 * q + 1];
                uint4 u;
                u.x = pack_bf16x2(a.x, a.y);
                u.y = pack_bf16x2(a.z, a.w);
                u.z = pack_bf16x2(b.x, b.y);
                u.w = pack_bf16x2(b.z, b.w);
                dst[q] = u;
            }
        }
        __syncwarp();

        // ---- layer 1: acc = inA(rows r0..r0+15) @ W1a ----
#pragma unroll
        for (int n = 0; n < 4; n++) wmma::fill_fragment(acc[n], 0.0f);
#pragma unroll
        for (int k = 0; k < 4; k++) {
            wmma::load_matrix_sync(af, inA + r0 * LDB + k * 16, LDB);
#pragma unroll
            for (int n = 0; n < 4; n++) {
                wmma::load_matrix_sync(bf, sW1a + (k * 16) * LDB + n * 16, LDB);
                wmma::mma_sync(acc[n], af, bf, acc[n]);
            }
        }
#pragma unroll
        for (int n = 0; n < 4; n++)
            wmma::store_matrix_sync(sD + r0 * LDD + n * 16, acc[n], LDD, wmma::mem_row_major);
        __syncwarp();

        // ---- bias + relu + bf16 requantize: D -> inA (own rows, in place) ----
        {
            const float* drow = sD + myrow * LDD + half * 32;
            const float* brow = sb1a + half * 32;
            uint4* hdst = (uint4*)(inA + myrow * LDB + half * 32);
#pragma unroll
            for (int q = 0; q < 4; q++) {
                float4 a = ((const float4*)drow)[2 * q];
                float4 b = ((const float4*)drow)[2 * q + 1];
                uint4 u;
                u.x = pack_bf16x2(fmaxf(a.x + brow[q * 8 + 0], 0.f), fmaxf(a.y + brow[q * 8 + 1], 0.f));
                u.y = pack_bf16x2(fmaxf(a.z + brow[q * 8 + 2], 0.f), fmaxf(a.w + brow[q * 8 + 3], 0.f));
                u.z = pack_bf16x2(fmaxf(b.x + brow[q * 8 + 4], 0.f), fmaxf(b.y + brow[q * 8 + 5], 0.f));
                u.w = pack_bf16x2(fmaxf(b.z + brow[q * 8 + 6], 0.f), fmaxf(b.w + brow[q * 8 + 7], 0.f));
                hdst[q] = u;
            }
        }
        __syncwarp();

        // ---- layer 2: acc = hidden @ W1b ----
#pragma unroll
        for (int n = 0; n < 4; n++) wmma::fill_fragment(acc[n], 0.0f);
#pragma unroll
        for (int k = 0; k < 4; k++) {
            wmma::load_matrix_sync(af, inA + r0 * LDB + k * 16, LDB);
#pragma unroll
            for (int n = 0; n < 4; n++) {
                wmma::load_matrix_sync(bf, sW1b + (k * 16) * LDB + n * 16, LDB);
                wmma::mma_sync(acc[n], af, bf, acc[n]);
            }
        }
#pragma unroll
        for (int n = 0; n < 4; n++)
            wmma::store_matrix_sync(sD + r0 * LDD + n * 16, acc[n], LDD, wmma::mem_row_major);
        __syncwarp();

        // ---- scatter: g_summed[row] += D + b1b ----
        {
            const int row = eidx[e];
            const float* drow = sD + myrow * LDD + half * 32;
            const float* brow = sb1b + half * 32;
            float* base = g_summed + (size_t)row * 64 + half * 32;
#pragma unroll
            for (int q = 0; q < 8; q++) {
                float4 v = ((const float4*)drow)[q];
                red_add_v4(base + q * 4,
                           v.x + brow[q * 4 + 0], v.y + brow[q * 4 + 1],
                           v.z + brow[q * 4 + 2], v.w + brow[q * 4 + 3]);
            }
            if (!half) atomicAdd(&g_counts[row], 1.0f);
        }
        __syncwarp();
    }
}

// ---------------------------------------------------------------------------
// Node kernel (fp32 path — 63 us measured, unchanged)
// ---------------------------------------------------------------------------
extern __shared__ float smemf[];

__global__ __launch_bounds__(256) void node_kernel(
    const float* __restrict__ x,
    const float* __restrict__ W2a, const float* __restrict__ b2a,
    const float* __restrict__ W2b, const float* __restrict__ b2b,
    float* __restrict__ out)
{
    float* sW2a = smemf;                   // 96*64
    float* sW2b = sW2a + 6144;             // 64*32
    float* sB2a = sW2b + 2048;             // 64
    float* sB2b = sB2a + 64;               // 32
    float* inT  = sB2b + 32;               // [96 k][68]
    float* hT   = inT + 96 * PADW;         // [64 j][68]

    const int t = threadIdx.x;
    const int n0 = blockIdx.x * 64;

    {
        const float4* gA = (const float4*)W2a;
        float4* sA = (float4*)sW2a;
#pragma unroll
        for (int i = 0; i < 6; i++) sA[t + 256 * i] = gA[t + 256 * i];
        const float4* gB = (const float4*)W2b;
        float4* sB = (float4*)sW2b;
#pragma unroll
        for (int i = 0; i < 2; i++) sB[t + 256 * i] = gB[t + 256 * i];
    }
    if (t < 64) sB2a[t] = b2a[t];
    if (t < 32) sB2b[t] = b2b[t];

    {
        const int f4 = t & 7;
        const int n  = t >> 3;
#pragma unroll
        for (int pass = 0; pass < 2; pass++) {
            const int nn = n + pass * 32;
            const int node = n0 + nn;
            float4 v = make_float4(0.f, 0.f, 0.f, 0.f);
            if (node < NN) v = ((const float4*)x)[node * 8 + f4];
            inT[(f4 * 4 + 0) * PADW + nn] = v.x;
            inT[(f4 * 4 + 1) * PADW + nn] = v.y;
            inT[(f4 * 4 + 2) * PADW + nn] = v.z;
            inT[(f4 * 4 + 3) * PADW + nn] = v.w;
        }
    }
    {
        const int j4 = t & 15;
        const int n  = t >> 4;
#pragma unroll
        for (int pass = 0; pass < 4; pass++) {
            const int nn = n + pass * 16;
            const int node = n0 + nn;
            float4 v = make_float4(0.f, 0.f, 0.f, 0.f);
            if (node < NN) {
                const float inv = 1.0f / fmaxf(g_counts[node], 1.0f);
                v = ((const float4*)g_summed)[node * 16 + j4];
                v.x *= inv; v.y *= inv; v.z *= inv; v.w *= inv;
            }
            inT[(32 + j4 * 4 + 0) * PADW + nn] = v.x;
            inT[(32 + j4 * 4 + 1) * PADW + nn] = v.y;
            inT[(32 + j4 * 4 + 2) * PADW + nn] = v.z;
            inT[(32 + j4 * 4 + 3) * PADW + nn] = v.w;
        }
    }
    __syncthreads();

    const int e0 = (t & 15) * 4;

    {
        const int j0 = (t >> 4) * 4;
        float acc[4][4];
#pragma unroll
        for (int i = 0; i < 4; i++)
#pragma unroll
            for (int j = 0; j < 4; j++) acc[i][j] = 0.f;

#pragma unroll 8
        for (int k = 0; k < 96; k++) {
            const float4 av = *(const float4*)&inT[k * PADW + e0];
            const float4 wv = *(const float4*)&sW2a[k * 64 + j0];
            const float aa[4] = {av.x, av.y, av.z, av.w};
            const float ww[4] = {wv.x, wv.y, wv.z, wv.w};
#pragma unroll
            for (int i = 0; i < 4; i++)
#pragma unroll
                for (int j = 0; j < 4; j++) acc[i][j] += aa[i] * ww[j];
        }
#pragma unroll
        for (int j = 0; j < 4; j++) {
            const float b = sB2a[j0 + j];
            float4 v;
            v.x = fmaxf(acc[0][j] + b, 0.f);
            v.y = fmaxf(acc[1][j] + b, 0.f);
            v.z = fmaxf(acc[2][j] + b, 0.f);
            v.w = fmaxf(acc[3][j] + b, 0.f);
            *(float4*)&hT[(j0 + j) * PADW + e0] = v;
        }
    }
    __syncthreads();

    if (t < 128) {
        const int o0 = (t >> 4) * 4;
        float acc[4][4];
#pragma unroll
        for (int i = 0; i < 4; i++)
#pragma unroll
            for (int j = 0; j < 4; j++) acc[i][j] = 0.f;

#pragma unroll 8
        for (int k = 0; k < 64; k++) {
            const float4 av = *(const float4*)&hT[k * PADW + e0];
            const float4 wv = *(const float4*)&sW2b[k * 32 + o0];
            const float aa[4] = {av.x, av.y, av.z, av.w};
            const float ww[4] = {wv.x, wv.y, wv.z, wv.w};
#pragma unroll
            for (int i = 0; i < 4; i++)
#pragma unroll
                for (int j = 0; j < 4; j++) acc[i][j] += aa[i] * ww[j];
        }
#pragma unroll
        for (int i = 0; i < 4; i++) {
            const int node = n0 + e0 + i;
            if (node < NN) {
                float4 v;
                v.x = acc[i][0] + sB2b[o0 + 0];
                v.y = acc[i][1] + sB2b[o0 + 1];
                v.z = acc[i][2] + sB2b[o0 + 2];
                v.w = acc[i][3] + sB2b[o0 + 3];
                *(float4*)&out[node * 32 + o0] = v;
            }
        }
    }
}

// ---------------------------------------------------------------------------
extern "C" void kernel_launch(void* const* d_in, const int* in_sizes, int n_in,
                              void* d_out, int out_size)
{
    const float* x     = (const float*)d_in[0];
    const int*   eidx  = (const int*)d_in[1];    // int64 coerced to int32 by harness
    const float* eattr = (const float*)d_in[2];
    const float* W1a = (const float*)d_in[5];
    const float* b1a = (const float*)d_in[6];
    const float* W1b = (const float*)d_in[7];
    const float* b1b = (const float*)d_in[8];
    const float* W2a = (const float*)d_in[9];
    const float* b2a = (const float*)d_in[10];
    const float* W2b = (const float*)d_in[11];
    const float* b2b = (const float*)d_in[12];
    float* out = (float*)d_out;

    const size_t smem2 = (6144 + 2048 + 64 + 32 + 96 * PADW + 64 * PADW) * sizeof(float);

    cudaFuncSetAttribute(edge_kernel_bf16, cudaFuncAttributeMaxDynamicSharedMemorySize, EDGE_SMEM_BYTES);
    cudaFuncSetAttribute(node_kernel, cudaFuncAttributeMaxDynamicSharedMemorySize, (int)smem2);

    void* p_summed = nullptr;
    void* p_counts = nullptr;
    cudaGetSymbolAddress(&p_summed, g_summed);
    cudaGetSymbolAddress(&p_counts, g_counts);
    cudaMemsetAsync(p_summed, 0, (size_t)NN * 64 * sizeof(float));
    cudaMemsetAsync(p_counts, 0, (size_t)NN * sizeof(float));

    edge_kernel_bf16<<<444, 256, EDGE_SMEM_BYTES>>>(x, eidx, eattr, W1a, b1a, W1b, b1b);
    node_kernel<<<(NN + 63) / 64, 256, smem2>>>(x, W2a, b2a, W2b, b2b, out);
}

// round 16
// speedup vs baseline: 2.5767x; 1.4947x over previous
#include <cuda_runtime.h>
#include <cuda_bf16.h>
#include <mma.h>
#include <cstdint>

using namespace nvcuda;

#define E_TOTAL 1600000
#define NN      100000
#define NTILES  (E_TOTAL / 128)   // 12500
#define PADW    68                // node kernel padding
#define LDB     72                // bf16 smem stride (72 el = 144 B)
#define LDD     68                // fp32 D-scratch stride

// Scratch (allocation-free rule: __device__ globals)
__device__ float g_summed[NN * 64];
__device__ float g_counts[NN];

__device__ __forceinline__ void red_add_v4(float* p, float a, float b, float c, float d) {
    asm volatile("red.global.add.v4.f32 [%0], {%1, %2, %3, %4};"
                 :: "l"(p), "f"(a), "f"(b), "f"(c), "f"(d) : "memory");
}
__device__ __forceinline__ uint32_t pack_bf16x2(float lo, float hi) {
    __nv_bfloat162 h = __floats2bfloat162_rn(lo, hi);
    return *(uint32_t*)&h;
}

// Edge-kernel dynamic smem (byte offsets; all 16B aligned):
//   sW1a bf16[64][72]  @0      (9216 B)
//   sW1b bf16[64][72]  @9216   (9216 B)
//   inA  bf16[128][72] @18432  (18432 B)
//   sD   f32 [128][68] @36864  (34816 B)
//   b1a  f32 [64]      @71680, b1b f32[64] @71936
#define EDGE_SMEM_BYTES 72192    // -> 3 CTAs/SM

extern __shared__ char esm8[];

// ---------------------------------------------------------------------------
// Edge kernel: persistent, bf16 wmma (HMMA.16816 + LDSM). 128 edges/tile,
// 8 warps, each warp owns an independent 16-edge pipeline.
// Gather and scatter are line-coalesced: every memory instruction covers
// whole 128B rows (4 wavefronts/inst instead of ~32).
// ---------------------------------------------------------------------------
__global__ __launch_bounds__(256) void edge_kernel_bf16(
    const float* __restrict__ x,
    const int* __restrict__ eidx,
    const float* __restrict__ eattr,
    const float* __restrict__ W1a, const float* __restrict__ b1a,
    const float* __restrict__ W1b, const float* __restrict__ b1b)
{
    const int tid = threadIdx.x;
    const int w   = tid >> 5;
    const int ln  = tid & 31;

    __nv_bfloat16* sW1a = (__nv_bfloat16*)(esm8);
    __nv_bfloat16* sW1b = (__nv_bfloat16*)(esm8 + 9216);
    __nv_bfloat16* inA  = (__nv_bfloat16*)(esm8 + 18432);
    float* sD   = (float*)(esm8 + 36864);
    float* sb1a = (float*)(esm8 + 71680);
    float* sb1b = (float*)(esm8 + 71936);

    // ---- stage weights (bf16) + biases, once per CTA ----
    for (int idx = tid; idx < 4096; idx += 256) {
        const int k = idx >> 6, n = idx & 63;
        sW1a[k * LDB + n] = __float2bfloat16(W1a[idx]);
        sW1b[k * LDB + n] = __float2bfloat16(W1b[idx]);
    }
    if (tid < 64) {
        sb1a[tid] = b1a[tid];
        sb1b[tid] = b1b[tid];
    }
    __syncthreads();

    const int i    = ln >> 1;      // edge-in-warp (requant mapping)
    const int half = ln & 1;
    const int r0   = w * 16;
    const int myrow = r0 + i;

    wmma::fragment<wmma::matrix_a, 16, 16, 16, __nv_bfloat16, wmma::row_major> af;
    wmma::fragment<wmma::matrix_b, 16, 16, 16, __nv_bfloat16, wmma::row_major> bf;
    wmma::fragment<wmma::accumulator, 16, 16, 16, float> acc[4];

    for (int tile = blockIdx.x; tile < NTILES; tile += gridDim.x) {
        const int ebase = tile * 128 + r0;   // this warp's first edge

        // lanes 0..15 hold row/col indices for the warp's 16 edges
        int rowv = 0, colv = 0;
        if (ln < 16) {
            rowv = eidx[ebase + ln];
            colv = eidx[E_TOTAL + ebase + ln];
        }

        // ---- coalesced gather: each iter loads 4 full 128B rows (8 lanes/row)
        //      p=0..3: x[col]  -> inA[..][0..31];  p=4..7: eattr -> inA[..][32..63]
#pragma unroll
        for (int p = 0; p < 8; p++) {
            const int flat = p * 32 + ln;          // 0..255
            const int c    = flat & 7;             // float4 chunk in row
            const int ei   = (flat >> 3) & 15;     // edge in warp
            const int hf   = p >> 2;               // 0: x, 1: eattr
            const int col  = __shfl_sync(0xffffffff, colv, ei);
            const float4* srcrow = hf ? (const float4*)(eattr + (size_t)(ebase + ei) * 32)
                                      : (const float4*)(x + (size_t)col * 32);
            const float4 v = srcrow[c];
            uint2 u;
            u.x = pack_bf16x2(v.x, v.y);
            u.y = pack_bf16x2(v.z, v.w);
            *(uint2*)(inA + (r0 + ei) * LDB + hf * 32 + c * 4) = u;
        }
        __syncwarp();

        // ---- layer 1: acc = inA(rows r0..r0+15) @ W1a ----
#pragma unroll
        for (int n = 0; n < 4; n++) wmma::fill_fragment(acc[n], 0.0f);
#pragma unroll
        for (int k = 0; k < 4; k++) {
            wmma::load_matrix_sync(af, inA + r0 * LDB + k * 16, LDB);
#pragma unroll
            for (int n = 0; n < 4; n++) {
                wmma::load_matrix_sync(bf, sW1a + (k * 16) * LDB + n * 16, LDB);
                wmma::mma_sync(acc[n], af, bf, acc[n]);
            }
        }
#pragma unroll
        for (int n = 0; n < 4; n++)
            wmma::store_matrix_sync(sD + r0 * LDD + n * 16, acc[n], LDD, wmma::mem_row_major);
        __syncwarp();

        // ---- bias + relu + bf16 requantize: sD -> inA (smem only) ----
        {
            const float* drow = sD + myrow * LDD + half * 32;
            const float* brow = sb1a + half * 32;
            uint4* hdst = (uint4*)(inA + myrow * LDB + half * 32);
#pragma unroll
            for (int q = 0; q < 4; q++) {
                float4 a = ((const float4*)drow)[2 * q];
                float4 b = ((const float4*)drow)[2 * q + 1];
                uint4 u;
                u.x = pack_bf16x2(fmaxf(a.x + brow[q * 8 + 0], 0.f), fmaxf(a.y + brow[q * 8 + 1], 0.f));
                u.y = pack_bf16x2(fmaxf(a.z + brow[q * 8 + 2], 0.f), fmaxf(a.w + brow[q * 8 + 3], 0.f));
                u.z = pack_bf16x2(fmaxf(b.x + brow[q * 8 + 4], 0.f), fmaxf(b.y + brow[q * 8 + 5], 0.f));
                u.w = pack_bf16x2(fmaxf(b.z + brow[q * 8 + 6], 0.f), fmaxf(b.w + brow[q * 8 + 7], 0.f));
                hdst[q] = u;
            }
        }
        __syncwarp();

        // ---- layer 2: acc = hidden @ W1b ----
#pragma unroll
        for (int n = 0; n < 4; n++) wmma::fill_fragment(acc[n], 0.0f);
#pragma unroll
        for (int k = 0; k < 4; k++) {
            wmma::load_matrix_sync(af, inA + r0 * LDB + k * 16, LDB);
#pragma unroll
            for (int n = 0; n < 4; n++) {
                wmma::load_matrix_sync(bf, sW1b + (k * 16) * LDB + n * 16, LDB);
                wmma::mma_sync(acc[n], af, bf, acc[n]);
            }
        }
#pragma unroll
        for (int n = 0; n < 4; n++)
            wmma::store_matrix_sync(sD + r0 * LDD + n * 16, acc[n], LDD, wmma::mem_row_major);
        __syncwarp();

        // ---- coalesced scatter: each iter covers 2 full 256B dest rows
        //      (16 lanes x 16B contiguous per row) ----
#pragma unroll
        for (int p = 0; p < 8; p++) {
            const int ei  = p * 2 + (ln >> 4);     // edge in warp
            const int fo  = (ln & 15) * 4;         // float offset 0..60
            const int row = __shfl_sync(0xffffffff, rowv, ei);
            const float4 v = *(const float4*)(sD + (r0 + ei) * LDD + fo);
            red_add_v4(g_summed + (size_t)row * 64 + fo,
                       v.x + sb1b[fo + 0], v.y + sb1b[fo + 1],
                       v.z + sb1b[fo + 2], v.w + sb1b[fo + 3]);
        }
        if (ln < 16) atomicAdd(&g_counts[rowv], 1.0f);
        __syncwarp();
    }
}

// ---------------------------------------------------------------------------
// Node kernel (fp32 path — 63 us measured, unchanged)
// ---------------------------------------------------------------------------
extern __shared__ float smemf[];

__global__ __launch_bounds__(256) void node_kernel(
    const float* __restrict__ x,
    const float* __restrict__ W2a, const float* __restrict__ b2a,
    const float* __restrict__ W2b, const float* __restrict__ b2b,
    float* __restrict__ out)
{
    float* sW2a = smemf;                   // 96*64
    float* sW2b = sW2a + 6144;             // 64*32
    float* sB2a = sW2b + 2048;             // 64
    float* sB2b = sB2a + 64;               // 32
    float* inT  = sB2b + 32;               // [96 k][68]
    float* hT   = inT + 96 * PADW;         // [64 j][68]

    const int t = threadIdx.x;
    const int n0 = blockIdx.x * 64;

    {
        const float4* gA = (const float4*)W2a;
        float4* sA = (float4*)sW2a;
#pragma unroll
        for (int i = 0; i < 6; i++) sA[t + 256 * i] = gA[t + 256 * i];
        const float4* gB = (const float4*)W2b;
        float4* sB = (float4*)sW2b;
#pragma unroll
        for (int i = 0; i < 2; i++) sB[t + 256 * i] = gB[t + 256 * i];
    }
    if (t < 64) sB2a[t] = b2a[t];
    if (t < 32) sB2b[t] = b2b[t];

    {
        const int f4 = t & 7;
        const int n  = t >> 3;
#pragma unroll
        for (int pass = 0; pass < 2; pass++) {
            const int nn = n + pass * 32;
            const int node = n0 + nn;
            float4 v = make_float4(0.f, 0.f, 0.f, 0.f);
            if (node < NN) v = ((const float4*)x)[node * 8 + f4];
            inT[(f4 * 4 + 0) * PADW + nn] = v.x;
            inT[(f4 * 4 + 1) * PADW + nn] = v.y;
            inT[(f4 * 4 + 2) * PADW + nn] = v.z;
            inT[(f4 * 4 + 3) * PADW + nn] = v.w;
        }
    }
    {
        const int j4 = t & 15;
        const int n  = t >> 4;
#pragma unroll
        for (int pass = 0; pass < 4; pass++) {
            const int nn = n + pass * 16;
            const int node = n0 + nn;
            float4 v = make_float4(0.f, 0.f, 0.f, 0.f);
            if (node < NN) {
                const float inv = 1.0f / fmaxf(g_counts[node], 1.0f);
                v = ((const float4*)g_summed)[node * 16 + j4];
                v.x *= inv; v.y *= inv; v.z *= inv; v.w *= inv;
            }
            inT[(32 + j4 * 4 + 0) * PADW + nn] = v.x;
            inT[(32 + j4 * 4 + 1) * PADW + nn] = v.y;
            inT[(32 + j4 * 4 + 2) * PADW + nn] = v.z;
            inT[(32 + j4 * 4 + 3) * PADW + nn] = v.w;
        }
    }
    __syncthreads();

    const int e0 = (t & 15) * 4;

    {
        const int j0 = (t >> 4) * 4;
        float acc[4][4];
#pragma unroll
        for (int i = 0; i < 4; i++)
#pragma unroll
            for (int j = 0; j < 4; j++) acc[i][j] = 0.f;

#pragma unroll 8
        for (int k = 0; k < 96; k++) {
            const float4 av = *(const float4*)&inT[k * PADW + e0];
            const float4 wv = *(const float4*)&sW2a[k * 64 + j0];
            const float aa[4] = {av.x, av.y, av.z, av.w};
            const float ww[4] = {wv.x, wv.y, wv.z, wv.w};
#pragma unroll
            for (int i = 0; i < 4; i++)
#pragma unroll
                for (int j = 0; j < 4; j++) acc[i][j] += aa[i] * ww[j];
        }
#pragma unroll
        for (int j = 0; j < 4; j++) {
            const float b = sB2a[j0 + j];
            float4 v;
            v.x = fmaxf(acc[0][j] + b, 0.f);
            v.y = fmaxf(acc[1][j] + b, 0.f);
            v.z = fmaxf(acc[2][j] + b, 0.f);
            v.w = fmaxf(acc[3][j] + b, 0.f);
            *(float4*)&hT[(j0 + j) * PADW + e0] = v;
        }
    }
    __syncthreads();

    if (t < 128) {
        const int o0 = (t >> 4) * 4;
        float acc[4][4];
#pragma unroll
        for (int i = 0; i < 4; i++)
#pragma unroll
            for (int j = 0; j < 4; j++) acc[i][j] = 0.f;

#pragma unroll 8
        for (int k = 0; k < 64; k++) {
            const float4 av = *(const float4*)&hT[k * PADW + e0];
            const float4 wv = *(const float4*)&sW2b[k * 32 + o0];
            const float aa[4] = {av.x, av.y, av.z, av.w};
            const float ww[4] = {wv.x, wv.y, wv.z, wv.w};
#pragma unroll
            for (int i = 0; i < 4; i++)
#pragma unroll
                for (int j = 0; j < 4; j++) acc[i][j] += aa[i] * ww[j];
        }
#pragma unroll
        for (int i = 0; i < 4; i++) {
            const int node = n0 + e0 + i;
            if (node < NN) {
                float4 v;
                v.x = acc[i][0] + sB2b[o0 + 0];
                v.y = acc[i][1] + sB2b[o0 + 1];
                v.z = acc[i][2] + sB2b[o0 + 2];
                v.w = acc[i][3] + sB2b[o0 + 3];
                *(float4*)&out[node * 32 + o0] = v;
            }
        }
    }
}

// ---------------------------------------------------------------------------
extern "C" void kernel_launch(void* const* d_in, const int* in_sizes, int n_in,
                              void* d_out, int out_size)
{
    const float* x     = (const float*)d_in[0];
    const int*   eidx  = (const int*)d_in[1];    // int64 coerced to int32 by harness
    const float* eattr = (const float*)d_in[2];
    const float* W1a = (const float*)d_in[5];
    const float* b1a = (const float*)d_in[6];
    const float* W1b = (const float*)d_in[7];
    const float* b1b = (const float*)d_in[8];
    const float* W2a = (const float*)d_in[9];
    const float* b2a = (const float*)d_in[10];
    const float* W2b = (const float*)d_in[11];
    const float* b2b = (const float*)d_in[12];
    float* out = (float*)d_out;

    const size_t smem2 = (6144 + 2048 + 64 + 32 + 96 * PADW + 64 * PADW) * sizeof(float);

    cudaFuncSetAttribute(edge_kernel_bf16, cudaFuncAttributeMaxDynamicSharedMemorySize, EDGE_SMEM_BYTES);
    cudaFuncSetAttribute(node_kernel, cudaFuncAttributeMaxDynamicSharedMemorySize, (int)smem2);

    void* p_summed = nullptr;
    void* p_counts = nullptr;
    cudaGetSymbolAddress(&p_summed, g_summed);
    cudaGetSymbolAddress(&p_counts, g_counts);
    cudaMemsetAsync(p_summed, 0, (size_t)NN * 64 * sizeof(float));
    cudaMemsetAsync(p_counts, 0, (size_t)NN * sizeof(float));

    edge_kernel_bf16<<<444, 256, EDGE_SMEM_BYTES>>>(x, eidx, eattr, W1a, b1a, W1b, b1b);
    node_kernel<<<(NN + 63) / 64, 256, smem2>>>(x, W2a, b2a, W2b, b2b, out);
}